// round 6
// baseline (speedup 1.0000x reference)
#include <cuda_runtime.h>
#include <cstdint>

#define LSEQ 96
#define DM 32
#define NNODES 2000

// 12.3 MB repacked complex frequency weights: [n][j4(12)][lane(32)][4 floats]
// lane = h*8+o ; per-lane j=0..47 -> e=j/6, r=j%6, m=r>>1, which=r&1 (0:W1,1:W2)
__device__ float g_Wc[(size_t)NNODES * 1536];

// ---------------- compile-time trig (constexpr Taylor, exact to ~1e-12) ----------------
__host__ __device__ constexpr double KPI = 3.14159265358979323846;
__host__ __device__ constexpr double tsin_(double x){ double x2=x*x;
  return x*(1 - x2/6*(1 - x2/20*(1 - x2/42*(1 - x2/72*(1 - x2/110*(1 - x2/156*(1 - x2/210)))))));
}
__host__ __device__ constexpr double tcos_(double x){ double x2=x*x;
  return 1 - x2/2*(1 - x2/12*(1 - x2/30*(1 - x2/56*(1 - x2/90*(1 - x2/132*(1 - x2/182))))));
}
__host__ __device__ constexpr double cs96(int k){ k=((k%96)+96)%96; int q=k/24, r=k%24; double x=r*(KPI/48);
  double c=tcos_(x), s=tsin_(x);
  return q==0? c : (q==1? -s : (q==2? -c : s)); }
__host__ __device__ constexpr double sn96(int k){ k=((k%96)+96)%96; int q=k/24, r=k%24; double x=r*(KPI/48);
  double c=tcos_(x), s=tsin_(x);
  return q==0? s : (q==1? c : (q==2? -s : -c)); }

// G_m(t): inverse-mode basis with edge-replicated moving-average detrend folded in.
__host__ __device__ constexpr double Gre_(int f, int t){
  int lo = (t-12 < 0) ? 0 : t-12;
  int hi = (t+12 > 95) ? 95 : t+12;
  double s = 0;
  for (int j = lo; j <= hi; ++j) s += cs96(f*j);
  if (t < 12)  s += (double)(12 - t) * cs96(0);
  if (t > 83)  s += (double)(t - 83) * cs96(f*95);
  return cs96(f*t) - s/25.0;
}
__host__ __device__ constexpr double Gim_(int f, int t){
  int lo = (t-12 < 0) ? 0 : t-12;
  int hi = (t+12 > 95) ? 95 : t+12;
  double s = 0;
  for (int j = lo; j <= hi; ++j) s += sn96(f*j);
  if (t < 12)  s += (double)(12 - t) * sn96(0);
  if (t > 83)  s += (double)(t - 83) * sn96(f*95);
  return sn96(f*t) - s/25.0;
}

// ---------------- W repack kernel (runs per launch; deterministic) ----------------
__global__ __launch_bounds__(384)
void repack_kernel(const float* __restrict__ W1, const float* __restrict__ W2)
{
    int n  = blockIdx.x;              // 0..1999
    int t  = threadIdx.x;             // 0..383  (j4 = t>>5, lane = t&31)
    int j4   = t >> 5;
    int lane = t & 31;
    int h = lane >> 3, o = lane & 7;
    float4 v;
    float r[4];
    #pragma unroll
    for (int k = 0; k < 4; ++k) {
        int j = j4 * 4 + k;
        int e = j / 6, rr = j % 6;
        int m = rr >> 1, which = rr & 1;
        size_t src = (size_t)n * 768 + (size_t)h * 192 + e * 24 + o * 3 + m;
        r[k] = which ? W2[src] : W1[src];
    }
    v.x = r[0]; v.y = r[1]; v.z = r[2]; v.w = r[3];
    ((float4*)g_Wc)[(size_t)n * 384 + j4 * 32 + lane] = v;
}

// ---------------- bulk copy + mbarrier helpers ----------------
__device__ __forceinline__ void mbar_init(unsigned int mbar, unsigned int cnt){
    asm volatile("mbarrier.init.shared.b64 [%0], %1;" :: "r"(mbar), "r"(cnt) : "memory");
}
__device__ __forceinline__ void mbar_expect_tx(unsigned int mbar, unsigned int bytes){
    asm volatile("mbarrier.arrive.expect_tx.shared.b64 _, [%0], %1;" :: "r"(mbar), "r"(bytes) : "memory");
}
__device__ __forceinline__ void bulk_g2s(unsigned int sdst, const void* gsrc, unsigned int bytes, unsigned int mbar){
    asm volatile("cp.async.bulk.shared::cta.global.mbarrier::complete_tx::bytes [%0], [%1], %2, [%3];"
                 :: "r"(sdst), "l"(gsrc), "r"(bytes), "r"(mbar) : "memory");
}
__device__ __forceinline__ void mbar_wait(unsigned int mbar, unsigned int parity){
    asm volatile(
        "{\n\t.reg .pred P1;\n\t"
        "WAIT_%=:\n\t"
        "mbarrier.try_wait.parity.acquire.cta.shared::cta.b64 P1, [%0], %1, 0x989680;\n\t"
        "@P1 bra.uni DONE_%=;\n\t"
        "bra.uni WAIT_%=;\n\t"
        "DONE_%=:\n\t}"
        :: "r"(mbar), "r"(parity) : "memory");
}

// ---------------- Phase B: 3-mode DFT with immediate trig ----------------
struct Acc6 { float ar0, ai0, ar1, ai1, ar2, ai2; };

template<int L> __device__ __forceinline__ void bstep(Acc6& a, const float* xp){
  float xv = xp[L*DM];
  constexpr float c0=(float)cs96(1*L), s0=(float)sn96(1*L);
  constexpr float c1=(float)cs96(4*L), s1=(float)sn96(4*L);
  constexpr float c2=(float)cs96(5*L), s2=(float)sn96(5*L);
  a.ar0=fmaf(xv,c0,a.ar0); a.ai0=fmaf(xv,-s0,a.ai0);
  a.ar1=fmaf(xv,c1,a.ar1); a.ai1=fmaf(xv,-s1,a.ai1);
  a.ar2=fmaf(xv,c2,a.ar2); a.ai2=fmaf(xv,-s2,a.ai2);
}
template<int L> __device__ __forceinline__ void bloop(Acc6& a, const float* xp){
  if constexpr (L < LSEQ){ bstep<L>(a, xp); bloop<L+1>(a, xp); }
}

// ---------------- fused inverse-transform + detrend (Phases F+G) ----------------
template<int T> __device__ __forceinline__ void fgstep(
    const float* xp, float* op, float ring[26], float& run, float x0, float& x95,
    float zr0, float zi0, float zr1, float zi1, float zr2, float zi2)
{
  float cur = ring[T % 26];
  constexpr float g0r=(float)Gre_(1,T), g0i=(float)Gim_(1,T);
  constexpr float g1r=(float)Gre_(4,T), g1i=(float)Gim_(4,T);
  constexpr float g2r=(float)Gre_(5,T), g2i=(float)Gim_(5,T);
  float oy = fmaf(zr0,g0r, fmaf(-zi0,g0i, fmaf(zr1,g1r, fmaf(-zi1,g1i, fmaf(zr2,g2r, -zi2*g2i)))));
  op[T*DM] = fmaf(run, -(1.0f/25.0f), cur) + oy;
  float subv = (T-12 >= 0) ? ring[(T+14) % 26] : x0;
  float addv;
  if constexpr (T+13 <= 95) addv = xp[(T+13)*DM]; else addv = x95;
  if constexpr (T+13 == 95) x95 = addv;
  ring[(T+13) % 26] = addv;
  run += addv - subv;
}
template<int T> __device__ __forceinline__ void fgloop(
    const float* xp, float* op, float ring[26], float& run, float x0, float& x95,
    float zr0, float zi0, float zr1, float zi1, float zr2, float zi2)
{
  if constexpr (T < LSEQ){
    fgstep<T>(xp, op, ring, run, x0, x95, zr0, zi0, zr1, zi1, zr2, zi2);
    fgloop<T+1>(xp, op, ring, run, x0, x95, zr0, zi0, zr1, zi1, zr2, zi2);
  }
}

// One warp per (b,n) tile of [96 x 32], lane == channel d. 2 warps/block, grid 8000.
__global__ __launch_bounds__(64, 8)
void feldm_kernel(const float* __restrict__ x,
                  const float* __restrict__ Wq,
                  const float* __restrict__ Wo,
                  float* __restrict__ out)
{
    __shared__ float  xbuf[2][LSEQ * DM];                 // per-warp x tile (12KB each)
    __shared__ float4 scr4[2][DM];                        // exchange: modes 0,1
    __shared__ float2 scr2[2][DM];                        // exchange: mode 2
    __shared__ __align__(8) unsigned long long mbar[2];   // per-warp barrier

    const int tid  = threadIdx.x;
    const int warp = tid >> 5;
    const int lane = tid & 31;

    const int unit = blockIdx.x * 2 + warp;     // b*2000 + n
    const int n    = unit % 2000;
    const float* __restrict__ xu = x   + (size_t)unit * (LSEQ * DM);
    float* __restrict__       ou = out + (size_t)unit * (LSEQ * DM);

    // ---- stage x tile via 12KB bulk copy (TMA path, bypasses LSU wavefronts) ----
    unsigned int mb = (unsigned int)__cvta_generic_to_shared(&mbar[warp]);
    if (lane == 0) {
        mbar_init(mb, 1);
        asm volatile("fence.proxy.async.shared::cta;" ::: "memory");
    }
    __syncwarp();
    if (lane == 0) {
        unsigned int sdst = (unsigned int)__cvta_generic_to_shared(&xbuf[warp][0]);
        mbar_expect_tx(mb, LSEQ * DM * 4);
        bulk_g2s(sdst, xu, LSEQ * DM * 4, mb);
    }
    mbar_wait(mb, 0);
    __syncwarp();

    const float* xp = &xbuf[warp][lane];

    // ---- Phase B: 3-mode DFT along l (rfft sign e^{-iwl}) ----
    Acc6 a = {0.f,0.f,0.f,0.f,0.f,0.f};
    bloop<0>(a, xp);
    scr4[warp][lane] = make_float4(a.ar0, a.ai0, a.ar1, a.ai1);
    scr2[warp][lane] = make_float2(a.ar2, a.ai2);
    __syncwarp();

    // ---- Phase C: Xq[c,m] = sum_d Wq[c,d] * Xx[d,m]  (bq feeds only mode 0 -> drops) ----
    float wrow[32];
    #pragma unroll
    for (int j = 0; j < 8; ++j) {
        float4 v = *(const float4*)&Wq[lane * 32 + 4 * j];
        wrow[4*j] = v.x; wrow[4*j+1] = v.y; wrow[4*j+2] = v.z; wrow[4*j+3] = v.w;
    }
    float qr0=0.f,qi0=0.f,qr1=0.f,qi1=0.f,qr2=0.f,qi2=0.f;
    #pragma unroll
    for (int d = 0; d < 32; ++d) {
        float4 t0 = scr4[warp][d];
        float2 t1 = scr2[warp][d];
        float w = wrow[d];
        qr0 = fmaf(w, t0.x, qr0); qi0 = fmaf(w, t0.y, qi0);
        qr1 = fmaf(w, t0.z, qr1); qi1 = fmaf(w, t0.w, qi1);
        qr2 = fmaf(w, t1.x, qr2); qi2 = fmaf(w, t1.y, qi2);
    }
    __syncwarp();
    scr4[warp][lane] = make_float4(qr0, qi0, qr1, qi1);
    scr2[warp][lane] = make_float2(qr2, qi2);
    __syncwarp();

    // ---- Phase D: per-head complex 8x8 mix, repacked coalesced weights ----
    const int h = lane >> 3;
    float w[48];
    {
        const float4* wc = (const float4*)g_Wc + (size_t)n * 384 + lane;
        #pragma unroll
        for (int j4 = 0; j4 < 12; ++j4) {
            float4 v = wc[j4 * 32];       // warp reads contiguous 512B
            w[4*j4] = v.x; w[4*j4+1] = v.y; w[4*j4+2] = v.z; w[4*j4+3] = v.w;
        }
    }
    float or0=0.f,oi0=0.f,or1=0.f,oi1=0.f,or2=0.f,oi2=0.f;
    #pragma unroll
    for (int e = 0; e < 8; ++e) {
        float4 t0 = scr4[warp][h * 8 + e];
        float2 t1 = scr2[warp][h * 8 + e];
        float a0 = w[6*e+0], b0 = w[6*e+1];
        float a1 = w[6*e+2], b1 = w[6*e+3];
        float a2 = w[6*e+4], b2 = w[6*e+5];
        or0 += t0.x*a0 - t0.y*b0;  oi0 += t0.x*b0 + t0.y*a0;
        or1 += t0.z*a1 - t0.w*b1;  oi1 += t0.z*b1 + t0.w*a1;
        or2 += t1.x*a2 - t1.y*b2;  oi2 += t1.x*b2 + t1.y*a2;
    }
    __syncwarp();
    scr4[warp][lane] = make_float4(or0, oi0, or1, oi1);
    scr2[warp][lane] = make_float2(or2, oi2);
    __syncwarp();

    // ---- Phase E: Z[dout,m] = (2/96) * sum_c O[c,m] * Wo[dout,c] ----
    #pragma unroll
    for (int j = 0; j < 8; ++j) {
        float4 v = *(const float4*)&Wo[lane * 32 + 4 * j];
        wrow[4*j] = v.x; wrow[4*j+1] = v.y; wrow[4*j+2] = v.z; wrow[4*j+3] = v.w;
    }
    float zr0=0.f,zi0=0.f,zr1=0.f,zi1=0.f,zr2=0.f,zi2=0.f;
    #pragma unroll
    for (int c = 0; c < 32; ++c) {
        float4 t0 = scr4[warp][c];
        float2 t1 = scr2[warp][c];
        float wv = wrow[c];
        zr0 = fmaf(wv, t0.x, zr0); zi0 = fmaf(wv, t0.y, zi0);
        zr1 = fmaf(wv, t0.z, zr1); zi1 = fmaf(wv, t0.w, zi1);
        zr2 = fmaf(wv, t1.x, zr2); zi2 = fmaf(wv, t1.y, zi2);
    }
    const float inv = 2.0f / 96.0f;
    zr0 *= inv; zi0 *= inv; zr1 *= inv; zi1 *= inv; zr2 *= inv; zi2 *= inv;
    // bo cancels exactly in (xr - movavg(xr)): every window averages 25 values.

    // ---- Phases F+G fused: out[t] = (x[t] - run/25) + Re(sum_m Z_m G_m(t)) ----
    float ring[26];
    #pragma unroll
    for (int j = 0; j < 13; ++j) ring[j] = xp[j*DM];
    float x0 = ring[0], x95 = 0.f;
    float run = 12.0f * x0;
    #pragma unroll
    for (int j = 0; j < 13; ++j) run += ring[j];

    fgloop<0>(xp, ou + lane, ring, run, x0, x95, zr0, zi0, zr1, zi1, zr2, zi2);
}

extern "C" void kernel_launch(void* const* d_in, const int* in_sizes, int n_in,
                              void* d_out, int out_size) {
    // metadata order: x, Wq, bq, Wk, bk, Wv, bv, Wo, bo, W1, W2
    const float* x  = (const float*)d_in[0];
    const float* Wq = (const float*)d_in[1];
    const float* Wo = (const float*)d_in[7];
    const float* W1 = (const float*)d_in[9];
    const float* W2 = (const float*)d_in[10];
    repack_kernel<<<NNODES, 384>>>(W1, W2);
    feldm_kernel<<<8000, 64>>>(x, Wq, Wo, (float*)d_out);
}

// round 7
// speedup vs baseline: 1.1675x; 1.1675x over previous
#include <cuda_runtime.h>
#include <cstdint>

#define LSEQ 96
#define DM 32
#define NNODES 2000

// 12.3 MB repacked complex frequency weights: [n][j4(12)][lane(32)][4 floats]
// lane = h*8+o ; per-lane j=0..47 -> e=j/6, r=j%6, m=r>>1, which=r&1 (0:W1,1:W2)
__device__ float g_Wc[(size_t)NNODES * 1536];

// ---------------- compile-time trig (constexpr Taylor, exact to ~1e-12) ----------------
__host__ __device__ constexpr double KPI = 3.14159265358979323846;
__host__ __device__ constexpr double tsin_(double x){ double x2=x*x;
  return x*(1 - x2/6*(1 - x2/20*(1 - x2/42*(1 - x2/72*(1 - x2/110*(1 - x2/156*(1 - x2/210)))))));
}
__host__ __device__ constexpr double tcos_(double x){ double x2=x*x;
  return 1 - x2/2*(1 - x2/12*(1 - x2/30*(1 - x2/56*(1 - x2/90*(1 - x2/132*(1 - x2/182))))));
}
__host__ __device__ constexpr double cs96(int k){ k=((k%96)+96)%96; int q=k/24, r=k%24; double x=r*(KPI/48);
  double c=tcos_(x), s=tsin_(x);
  return q==0? c : (q==1? -s : (q==2? -c : s)); }
__host__ __device__ constexpr double sn96(int k){ k=((k%96)+96)%96; int q=k/24, r=k%24; double x=r*(KPI/48);
  double c=tcos_(x), s=tsin_(x);
  return q==0? s : (q==1? c : (q==2? -s : -c)); }

// G_m(t): inverse-mode basis with edge-replicated moving-average detrend folded in.
__host__ __device__ constexpr double Gre_(int f, int t){
  int lo = (t-12 < 0) ? 0 : t-12;
  int hi = (t+12 > 95) ? 95 : t+12;
  double s = 0;
  for (int j = lo; j <= hi; ++j) s += cs96(f*j);
  if (t < 12)  s += (double)(12 - t) * cs96(0);
  if (t > 83)  s += (double)(t - 83) * cs96(f*95);
  return cs96(f*t) - s/25.0;
}
__host__ __device__ constexpr double Gim_(int f, int t){
  int lo = (t-12 < 0) ? 0 : t-12;
  int hi = (t+12 > 95) ? 95 : t+12;
  double s = 0;
  for (int j = lo; j <= hi; ++j) s += sn96(f*j);
  if (t < 12)  s += (double)(12 - t) * sn96(0);
  if (t > 83)  s += (double)(t - 83) * sn96(f*95);
  return sn96(f*t) - s/25.0;
}

// ---------------- W repack kernel (per launch; deterministic, graph-safe) ----------------
__global__ __launch_bounds__(384)
void repack_kernel(const float* __restrict__ W1, const float* __restrict__ W2)
{
    int n  = blockIdx.x;
    int t  = threadIdx.x;             // j4 = t>>5, lane = t&31
    int j4   = t >> 5;
    int lane = t & 31;
    int h = lane >> 3, o = lane & 7;
    float r[4];
    #pragma unroll
    for (int k = 0; k < 4; ++k) {
        int j = j4 * 4 + k;
        int e = j / 6, rr = j % 6;
        int m = rr >> 1, which = rr & 1;
        size_t src = (size_t)n * 768 + (size_t)h * 192 + e * 24 + o * 3 + m;
        r[k] = which ? W2[src] : W1[src];
    }
    float4 v; v.x = r[0]; v.y = r[1]; v.z = r[2]; v.w = r[3];
    ((float4*)g_Wc)[(size_t)n * 384 + j4 * 32 + lane] = v;
}

// ---------------- Phase B: 3-mode DFT with immediate trig, x straight from GMEM ----------------
struct Acc6 { float ar0, ai0, ar1, ai1, ar2, ai2; };

template<int L> __device__ __forceinline__ void bstep(Acc6& a, const float* gx){
  float xv = gx[L*DM];                      // LDG, coalesced 128B/warp, caches in L1
  constexpr float c0=(float)cs96(1*L), s0=(float)sn96(1*L);
  constexpr float c1=(float)cs96(4*L), s1=(float)sn96(4*L);
  constexpr float c2=(float)cs96(5*L), s2=(float)sn96(5*L);
  a.ar0=fmaf(xv,c0,a.ar0); a.ai0=fmaf(xv,-s0,a.ai0);
  a.ar1=fmaf(xv,c1,a.ar1); a.ai1=fmaf(xv,-s1,a.ai1);
  a.ar2=fmaf(xv,c2,a.ar2); a.ai2=fmaf(xv,-s2,a.ai2);
}
template<int L> __device__ __forceinline__ void bloop(Acc6& a, const float* gx){
  if constexpr (L < LSEQ){ bstep<L>(a, gx); bloop<L+1>(a, gx); }
}

// ---------------- fused inverse-transform + detrend (Phases F+G), x re-read as L1 hits ----------------
template<int T> __device__ __forceinline__ void fgstep(
    const float* gx, float* op, float ring[26], float& run, float x0, float& x95,
    float zr0, float zi0, float zr1, float zi1, float zr2, float zi2)
{
  float cur = ring[T % 26];
  constexpr float g0r=(float)Gre_(1,T), g0i=(float)Gim_(1,T);
  constexpr float g1r=(float)Gre_(4,T), g1i=(float)Gim_(4,T);
  constexpr float g2r=(float)Gre_(5,T), g2i=(float)Gim_(5,T);
  float oy = fmaf(zr0,g0r, fmaf(-zi0,g0i, fmaf(zr1,g1r, fmaf(-zi1,g1i, fmaf(zr2,g2r, -zi2*g2i)))));
  op[T*DM] = fmaf(run, -(1.0f/25.0f), cur) + oy;
  float subv = (T-12 >= 0) ? ring[(T+14) % 26] : x0;
  float addv;
  if constexpr (T+13 <= 95) addv = gx[(T+13)*DM]; else addv = x95;   // L1 hit
  if constexpr (T+13 == 95) x95 = addv;
  ring[(T+13) % 26] = addv;
  run += addv - subv;
}
template<int T> __device__ __forceinline__ void fgloop(
    const float* gx, float* op, float ring[26], float& run, float x0, float& x95,
    float zr0, float zi0, float zr1, float zi1, float zr2, float zi2)
{
  if constexpr (T < LSEQ){
    fgstep<T>(gx, op, ring, run, x0, x95, zr0, zi0, zr1, zi1, zr2, zi2);
    fgloop<T+1>(gx, op, ring, run, x0, x95, zr0, zi0, zr1, zi1, zr2, zi2);
  }
}

// One warp per (b,n) tile of [96 x 32], lane == channel d. 2 warps/block, grid 8000.
__global__ __launch_bounds__(64, 8)
void feldm_kernel(const float* __restrict__ x,
                  const float* __restrict__ Wq,
                  const float* __restrict__ Wo,
                  float* __restrict__ out)
{
    __shared__ float4 scr4[2][DM];     // exchange: modes 0,1
    __shared__ float2 scr2[2][DM];     // exchange: mode 2

    const int tid  = threadIdx.x;
    const int warp = tid >> 5;
    const int lane = tid & 31;

    const int unit = blockIdx.x * 2 + warp;     // b*2000 + n
    const int n    = unit % 2000;
    const float* __restrict__ gx = x   + (size_t)unit * (LSEQ * DM) + lane;
    float* __restrict__       op = out + (size_t)unit * (LSEQ * DM) + lane;

    // ---- hoist Phase-D weight loads (coalesced LDG.128) to bury their latency ----
    const int h = lane >> 3;
    float w[48];
    {
        const float4* wc = (const float4*)g_Wc + (size_t)n * 384 + lane;
        #pragma unroll
        for (int j4 = 0; j4 < 12; ++j4) {
            float4 v = wc[j4 * 32];
            w[4*j4] = v.x; w[4*j4+1] = v.y; w[4*j4+2] = v.z; w[4*j4+3] = v.w;
        }
    }

    // ---- Phase B: 3-mode DFT along l (rfft sign e^{-iwl}) ----
    Acc6 a = {0.f,0.f,0.f,0.f,0.f,0.f};
    bloop<0>(a, gx);
    scr4[warp][lane] = make_float4(a.ar0, a.ai0, a.ar1, a.ai1);
    scr2[warp][lane] = make_float2(a.ar2, a.ai2);
    __syncwarp();

    // ---- Phase C: Xq[c,m] = sum_d Wq[c,d] * Xx[d,m]  (bq feeds only mode 0 -> drops) ----
    float wrow[32];
    #pragma unroll
    for (int j = 0; j < 8; ++j) {
        float4 v = *(const float4*)&Wq[lane * 32 + 4 * j];
        wrow[4*j] = v.x; wrow[4*j+1] = v.y; wrow[4*j+2] = v.z; wrow[4*j+3] = v.w;
    }
    float qr0=0.f,qi0=0.f,qr1=0.f,qi1=0.f,qr2=0.f,qi2=0.f;
    #pragma unroll
    for (int d = 0; d < 32; ++d) {
        float4 t0 = scr4[warp][d];
        float2 t1 = scr2[warp][d];
        float wv = wrow[d];
        qr0 = fmaf(wv, t0.x, qr0); qi0 = fmaf(wv, t0.y, qi0);
        qr1 = fmaf(wv, t0.z, qr1); qi1 = fmaf(wv, t0.w, qi1);
        qr2 = fmaf(wv, t1.x, qr2); qi2 = fmaf(wv, t1.y, qi2);
    }
    __syncwarp();
    scr4[warp][lane] = make_float4(qr0, qi0, qr1, qi1);
    scr2[warp][lane] = make_float2(qr2, qi2);
    __syncwarp();

    // ---- Phase D: per-head complex 8x8 mix (weights already in regs) ----
    float or0=0.f,oi0=0.f,or1=0.f,oi1=0.f,or2=0.f,oi2=0.f;
    #pragma unroll
    for (int e = 0; e < 8; ++e) {
        float4 t0 = scr4[warp][h * 8 + e];
        float2 t1 = scr2[warp][h * 8 + e];
        float a0 = w[6*e+0], b0 = w[6*e+1];
        float a1 = w[6*e+2], b1 = w[6*e+3];
        float a2 = w[6*e+4], b2 = w[6*e+5];
        or0 += t0.x*a0 - t0.y*b0;  oi0 += t0.x*b0 + t0.y*a0;
        or1 += t0.z*a1 - t0.w*b1;  oi1 += t0.z*b1 + t0.w*a1;
        or2 += t1.x*a2 - t1.y*b2;  oi2 += t1.x*b2 + t1.y*a2;
    }
    __syncwarp();
    scr4[warp][lane] = make_float4(or0, oi0, or1, oi1);
    scr2[warp][lane] = make_float2(or2, oi2);
    __syncwarp();

    // ---- Phase E: Z[dout,m] = (2/96) * sum_c O[c,m] * Wo[dout,c] ----
    #pragma unroll
    for (int j = 0; j < 8; ++j) {
        float4 v = *(const float4*)&Wo[lane * 32 + 4 * j];
        wrow[4*j] = v.x; wrow[4*j+1] = v.y; wrow[4*j+2] = v.z; wrow[4*j+3] = v.w;
    }
    float zr0=0.f,zi0=0.f,zr1=0.f,zi1=0.f,zr2=0.f,zi2=0.f;
    #pragma unroll
    for (int c = 0; c < 32; ++c) {
        float4 t0 = scr4[warp][c];
        float2 t1 = scr2[warp][c];
        float wv = wrow[c];
        zr0 = fmaf(wv, t0.x, zr0); zi0 = fmaf(wv, t0.y, zi0);
        zr1 = fmaf(wv, t0.z, zr1); zi1 = fmaf(wv, t0.w, zi1);
        zr2 = fmaf(wv, t1.x, zr2); zi2 = fmaf(wv, t1.y, zi2);
    }
    const float inv = 2.0f / 96.0f;
    zr0 *= inv; zi0 *= inv; zr1 *= inv; zi1 *= inv; zr2 *= inv; zi2 *= inv;
    // bo cancels exactly in (xr - movavg(xr)): every window averages 25 values.

    // ---- Phases F+G fused: out[t] = (x[t] - run/25) + Re(sum_m Z_m G_m(t)) ----
    float ring[26];
    #pragma unroll
    for (int j = 0; j < 13; ++j) ring[j] = gx[j*DM];   // L1 hits
    float x0 = ring[0], x95 = 0.f;
    float run = 12.0f * x0;
    #pragma unroll
    for (int j = 0; j < 13; ++j) run += ring[j];

    fgloop<0>(gx, op, ring, run, x0, x95, zr0, zi0, zr1, zi1, zr2, zi2);
}

extern "C" void kernel_launch(void* const* d_in, const int* in_sizes, int n_in,
                              void* d_out, int out_size) {
    // metadata order: x, Wq, bq, Wk, bk, Wv, bv, Wo, bo, W1, W2
    const float* x  = (const float*)d_in[0];
    const float* Wq = (const float*)d_in[1];
    const float* Wo = (const float*)d_in[7];
    const float* W1 = (const float*)d_in[9];
    const float* W2 = (const float*)d_in[10];
    repack_kernel<<<NNODES, 384>>>(W1, W2);
    feldm_kernel<<<8000, 64>>>(x, Wq, Wo, (float*)d_out);
}

// round 8
// speedup vs baseline: 1.5264x; 1.3073x over previous
#include <cuda_runtime.h>
#include <cstdint>

#define LSEQ 96
#define DM 32
#define NNODES 2000

// 12.3 MB repacked complex frequency weights: [n][j4(12)][lane(32)][4 floats]
// lane = h*8+o ; j = e*6 + m*2 + which (0:W1,1:W2); reg j <-> float (j>>2)*128 + lane*4 + (j&3)
__device__ float g_Wc[(size_t)NNODES * 1536];

// ---------------- compile-time trig (constexpr Taylor, exact to ~1e-12) ----------------
__host__ __device__ constexpr double KPI = 3.14159265358979323846;
__host__ __device__ constexpr double tsin_(double x){ double x2=x*x;
  return x*(1 - x2/6*(1 - x2/20*(1 - x2/42*(1 - x2/72*(1 - x2/110*(1 - x2/156*(1 - x2/210)))))));
}
__host__ __device__ constexpr double tcos_(double x){ double x2=x*x;
  return 1 - x2/2*(1 - x2/12*(1 - x2/30*(1 - x2/56*(1 - x2/90*(1 - x2/132*(1 - x2/182))))));
}
__host__ __device__ constexpr double cs96(int k){ k=((k%96)+96)%96; int q=k/24, r=k%24; double x=r*(KPI/48);
  double c=tcos_(x), s=tsin_(x);
  return q==0? c : (q==1? -s : (q==2? -c : s)); }
__host__ __device__ constexpr double sn96(int k){ k=((k%96)+96)%96; int q=k/24, r=k%24; double x=r*(KPI/48);
  double c=tcos_(x), s=tsin_(x);
  return q==0? s : (q==1? c : (q==2? -s : -c)); }

// G_m(t): inverse-mode basis with edge-replicated moving-average detrend folded in.
__host__ __device__ constexpr double Gre_(int f, int t){
  int lo = (t-12 < 0) ? 0 : t-12;
  int hi = (t+12 > 95) ? 95 : t+12;
  double s = 0;
  for (int j = lo; j <= hi; ++j) s += cs96(f*j);
  if (t < 12)  s += (double)(12 - t) * cs96(0);
  if (t > 83)  s += (double)(t - 83) * cs96(f*95);
  return cs96(f*t) - s/25.0;
}
__host__ __device__ constexpr double Gim_(int f, int t){
  int lo = (t-12 < 0) ? 0 : t-12;
  int hi = (t+12 > 95) ? 95 : t+12;
  double s = 0;
  for (int j = lo; j <= hi; ++j) s += sn96(f*j);
  if (t < 12)  s += (double)(12 - t) * sn96(0);
  if (t > 83)  s += (double)(t - 83) * sn96(f*95);
  return sn96(f*t) - s/25.0;
}

// ---------------- W repack kernel: coalesced in, smem scatter, coalesced out ----------------
__global__ __launch_bounds__(384)
void repack_kernel(const float* __restrict__ W1, const float* __restrict__ W2)
{
    __shared__ float s[1536];
    const int n = blockIdx.x;
    const int t = threadIdx.x;                  // 0..383

    #pragma unroll
    for (int half = 0; half < 2; ++half) {
        int src = half * 384 + t;               // 0..767, coalesced
        float v1 = W1[(size_t)n * 768 + src];
        float v2 = W2[(size_t)n * 768 + src];
        int h = src / 192, r = src % 192;
        int e = r / 24,   rr = r % 24;
        int o = rr / 3,   m  = rr % 3;
        int lane = h * 8 + o;
        int j1 = e * 6 + m * 2;                 // W1 slot
        s[(j1 >> 2) * 128 + lane * 4 + (j1 & 3)] = v1;
        int j2 = j1 + 1;                        // W2 slot
        s[(j2 >> 2) * 128 + lane * 4 + (j2 & 3)] = v2;
    }
    __syncthreads();
    float4 v = *(const float4*)&s[t * 4];
    ((float4*)g_Wc)[(size_t)n * 384 + t] = v;   // coalesced STG.128
}

// ---------------- TMA bulk + mbarrier helpers ----------------
__device__ __forceinline__ void mbar_init(unsigned int mbar, unsigned int cnt){
    asm volatile("mbarrier.init.shared.b64 [%0], %1;" :: "r"(mbar), "r"(cnt) : "memory");
}
__device__ __forceinline__ void mbar_expect_tx(unsigned int mbar, unsigned int bytes){
    asm volatile("mbarrier.arrive.expect_tx.shared.b64 _, [%0], %1;" :: "r"(mbar), "r"(bytes) : "memory");
}
__device__ __forceinline__ void bulk_g2s(unsigned int sdst, const void* gsrc, unsigned int bytes, unsigned int mbar){
    asm volatile("cp.async.bulk.shared::cta.global.mbarrier::complete_tx::bytes [%0], [%1], %2, [%3];"
                 :: "r"(sdst), "l"(gsrc), "r"(bytes), "r"(mbar) : "memory");
}
__device__ __forceinline__ void mbar_wait(unsigned int mbar, unsigned int parity){
    asm volatile(
        "{\n\t.reg .pred P1;\n\t"
        "WAIT_%=:\n\t"
        "mbarrier.try_wait.parity.acquire.cta.shared::cta.b64 P1, [%0], %1, 0x989680;\n\t"
        "@P1 bra.uni DONE_%=;\n\t"
        "bra.uni WAIT_%=;\n\t"
        "DONE_%=:\n\t}"
        :: "r"(mbar), "r"(parity) : "memory");
}

// ---------------- Phase B: 3-mode DFT with immediate trig (smem source) ----------------
struct Acc6 { float ar0, ai0, ar1, ai1, ar2, ai2; };

template<int L> __device__ __forceinline__ void bstep(Acc6& a, const float* xp){
  float xv = xp[L*DM];
  constexpr float c0=(float)cs96(1*L), s0=(float)sn96(1*L);
  constexpr float c1=(float)cs96(4*L), s1=(float)sn96(4*L);
  constexpr float c2=(float)cs96(5*L), s2=(float)sn96(5*L);
  a.ar0=fmaf(xv,c0,a.ar0); a.ai0=fmaf(xv,-s0,a.ai0);
  a.ar1=fmaf(xv,c1,a.ar1); a.ai1=fmaf(xv,-s1,a.ai1);
  a.ar2=fmaf(xv,c2,a.ar2); a.ai2=fmaf(xv,-s2,a.ai2);
}
template<int L> __device__ __forceinline__ void bloop(Acc6& a, const float* xp){
  if constexpr (L < LSEQ){ bstep<L>(a, xp); bloop<L+1>(a, xp); }
}

// ---------------- fused inverse-transform + detrend (Phases F+G, smem source) ----------------
template<int T> __device__ __forceinline__ void fgstep(
    const float* xp, float* op, float ring[26], float& run, float x0, float& x95,
    float zr0, float zi0, float zr1, float zi1, float zr2, float zi2)
{
  float cur = ring[T % 26];
  constexpr float g0r=(float)Gre_(1,T), g0i=(float)Gim_(1,T);
  constexpr float g1r=(float)Gre_(4,T), g1i=(float)Gim_(4,T);
  constexpr float g2r=(float)Gre_(5,T), g2i=(float)Gim_(5,T);
  float oy = fmaf(zr0,g0r, fmaf(-zi0,g0i, fmaf(zr1,g1r, fmaf(-zi1,g1i, fmaf(zr2,g2r, -zi2*g2i)))));
  op[T*DM] = fmaf(run, -(1.0f/25.0f), cur) + oy;
  float subv = (T-12 >= 0) ? ring[(T+14) % 26] : x0;
  float addv;
  if constexpr (T+13 <= 95) addv = xp[(T+13)*DM]; else addv = x95;
  if constexpr (T+13 == 95) x95 = addv;
  ring[(T+13) % 26] = addv;
  run += addv - subv;
}
template<int T> __device__ __forceinline__ void fgloop(
    const float* xp, float* op, float ring[26], float& run, float x0, float& x95,
    float zr0, float zi0, float zr1, float zi1, float zr2, float zi2)
{
  if constexpr (T < LSEQ){
    fgstep<T>(xp, op, ring, run, x0, x95, zr0, zi0, zr1, zi1, zr2, zi2);
    fgloop<T+1>(xp, op, ring, run, x0, x95, zr0, zi0, zr1, zi1, zr2, zi2);
  }
}

// One warp per (b,n) tile of [96 x 32], lane == channel d. 2 warps/block, grid 8000.
__global__ __launch_bounds__(64, 8)
void feldm_kernel(const float* __restrict__ x,
                  const float* __restrict__ Wq,
                  const float* __restrict__ Wo,
                  float* __restrict__ out)
{
    __shared__ __align__(16) float xbuf[2][LSEQ * DM];    // per-warp x tile (12KB each)
    __shared__ float4 scr4[2][DM];                        // exchange: modes 0,1
    __shared__ float2 scr2[2][DM];                        // exchange: mode 2
    __shared__ __align__(8) unsigned long long mbar[2];

    const int tid  = threadIdx.x;
    const int warp = tid >> 5;
    const int lane = tid & 31;

    const int unit = blockIdx.x * 2 + warp;     // b*2000 + n
    const int n    = unit % 2000;
    const float* __restrict__ xu = x   + (size_t)unit * (LSEQ * DM);
    float* __restrict__       op = out + (size_t)unit * (LSEQ * DM) + lane;

    // ---- issue 12KB TMA bulk copy early ----
    unsigned int mb = (unsigned int)__cvta_generic_to_shared(&mbar[warp]);
    if (lane == 0) {
        mbar_init(mb, 1);
        asm volatile("fence.proxy.async.shared::cta;" ::: "memory");
    }
    __syncwarp();
    if (lane == 0) {
        unsigned int sdst = (unsigned int)__cvta_generic_to_shared(&xbuf[warp][0]);
        mbar_expect_tx(mb, LSEQ * DM * 4);
        bulk_g2s(sdst, xu, LSEQ * DM * 4, mb);
    }

    // ---- overlap TMA latency: load per-node weights (coalesced) and Wq rows ----
    const int h = lane >> 3;
    float w[48];
    {
        const float4* wc = (const float4*)g_Wc + (size_t)n * 384 + lane;
        #pragma unroll
        for (int j4 = 0; j4 < 12; ++j4) {
            float4 v = wc[j4 * 32];
            w[4*j4] = v.x; w[4*j4+1] = v.y; w[4*j4+2] = v.z; w[4*j4+3] = v.w;
        }
    }
    float wrow[32];
    #pragma unroll
    for (int j = 0; j < 8; ++j) {
        float4 v = *(const float4*)&Wq[lane * 32 + 4 * j];
        wrow[4*j] = v.x; wrow[4*j+1] = v.y; wrow[4*j+2] = v.z; wrow[4*j+3] = v.w;
    }

    mbar_wait(mb, 0);
    __syncwarp();

    const float* xp = &xbuf[warp][lane];

    // ---- Phase B: 3-mode DFT along l (rfft sign e^{-iwl}) ----
    Acc6 a = {0.f,0.f,0.f,0.f,0.f,0.f};
    bloop<0>(a, xp);
    scr4[warp][lane] = make_float4(a.ar0, a.ai0, a.ar1, a.ai1);
    scr2[warp][lane] = make_float2(a.ar2, a.ai2);
    __syncwarp();

    // ---- Phase C: Xq[c,m] = sum_d Wq[c,d] * Xx[d,m]  (bq feeds only mode 0 -> drops) ----
    float qr0=0.f,qi0=0.f,qr1=0.f,qi1=0.f,qr2=0.f,qi2=0.f;
    #pragma unroll
    for (int d = 0; d < 32; ++d) {
        float4 t0 = scr4[warp][d];
        float2 t1 = scr2[warp][d];
        float wv = wrow[d];
        qr0 = fmaf(wv, t0.x, qr0); qi0 = fmaf(wv, t0.y, qi0);
        qr1 = fmaf(wv, t0.z, qr1); qi1 = fmaf(wv, t0.w, qi1);
        qr2 = fmaf(wv, t1.x, qr2); qi2 = fmaf(wv, t1.y, qi2);
    }
    __syncwarp();
    scr4[warp][lane] = make_float4(qr0, qi0, qr1, qi1);
    scr2[warp][lane] = make_float2(qr2, qi2);
    __syncwarp();

    // ---- Phase D: per-head complex 8x8 mix (weights already in regs) ----
    float or0=0.f,oi0=0.f,or1=0.f,oi1=0.f,or2=0.f,oi2=0.f;
    #pragma unroll
    for (int e = 0; e < 8; ++e) {
        float4 t0 = scr4[warp][h * 8 + e];
        float2 t1 = scr2[warp][h * 8 + e];
        float a0 = w[6*e+0], b0 = w[6*e+1];
        float a1 = w[6*e+2], b1 = w[6*e+3];
        float a2 = w[6*e+4], b2 = w[6*e+5];
        or0 += t0.x*a0 - t0.y*b0;  oi0 += t0.x*b0 + t0.y*a0;
        or1 += t0.z*a1 - t0.w*b1;  oi1 += t0.z*b1 + t0.w*a1;
        or2 += t1.x*a2 - t1.y*b2;  oi2 += t1.x*b2 + t1.y*a2;
    }
    __syncwarp();
    scr4[warp][lane] = make_float4(or0, oi0, or1, oi1);
    scr2[warp][lane] = make_float2(or2, oi2);
    __syncwarp();

    // ---- Phase E: Z[dout,m] = (2/96) * sum_c O[c,m] * Wo[dout,c] ----
    #pragma unroll
    for (int j = 0; j < 8; ++j) {
        float4 v = *(const float4*)&Wo[lane * 32 + 4 * j];
        wrow[4*j] = v.x; wrow[4*j+1] = v.y; wrow[4*j+2] = v.z; wrow[4*j+3] = v.w;
    }
    float zr0=0.f,zi0=0.f,zr1=0.f,zi1=0.f,zr2=0.f,zi2=0.f;
    #pragma unroll
    for (int c = 0; c < 32; ++c) {
        float4 t0 = scr4[warp][c];
        float2 t1 = scr2[warp][c];
        float wv = wrow[c];
        zr0 = fmaf(wv, t0.x, zr0); zi0 = fmaf(wv, t0.y, zi0);
        zr1 = fmaf(wv, t0.z, zr1); zi1 = fmaf(wv, t0.w, zi1);
        zr2 = fmaf(wv, t1.x, zr2); zi2 = fmaf(wv, t1.y, zi2);
    }
    const float inv = 2.0f / 96.0f;
    zr0 *= inv; zi0 *= inv; zr1 *= inv; zi1 *= inv; zr2 *= inv; zi2 *= inv;
    // bo cancels exactly in (xr - movavg(xr)): every window averages 25 values.

    // ---- Phases F+G fused: out[t] = (x[t] - run/25) + Re(sum_m Z_m G_m(t)) ----
    float ring[26];
    #pragma unroll
    for (int j = 0; j < 13; ++j) ring[j] = xp[j*DM];
    float x0 = ring[0], x95 = 0.f;
    float run = 12.0f * x0;
    #pragma unroll
    for (int j = 0; j < 13; ++j) run += ring[j];

    fgloop<0>(xp, op, ring, run, x0, x95, zr0, zi0, zr1, zi1, zr2, zi2);
}

extern "C" void kernel_launch(void* const* d_in, const int* in_sizes, int n_in,
                              void* d_out, int out_size) {
    // metadata order: x, Wq, bq, Wk, bk, Wv, bv, Wo, bo, W1, W2
    const float* x  = (const float*)d_in[0];
    const float* Wq = (const float*)d_in[1];
    const float* Wo = (const float*)d_in[7];
    const float* W1 = (const float*)d_in[9];
    const float* W2 = (const float*)d_in[10];
    repack_kernel<<<NNODES, 384>>>(W1, W2);
    feldm_kernel<<<8000, 64>>>(x, Wq, Wo, (float*)d_out);
}